// round 1
// baseline (speedup 1.0000x reference)
#include <cuda_runtime.h>

// RoiPoolingConv: img (16, 64, 64, 512) fp32 NHWC -> out (16, 16, 7, 7, 512)
// 16 ROIs tile the image as a 4x4 grid of 16x16 crops; each crop is bilinear-
// resized to 7x7 (jax half-pixel convention, antialias=False).
//
// Pure streaming gather-blend: source row/col pairs are disjoint across output
// pixels, so no reuse exists. One block per output pixel; each of 128 threads
// handles one float4 channel chunk (512 channels / 4).

__global__ __launch_bounds__(128, 8)
void roi_resize_kernel(const float* __restrict__ img, float* __restrict__ out) {
    const int tid = threadIdx.x;          // float4 chunk within channels: 0..127
    int p = blockIdx.x;                   // output pixel id: ((b*16 + r)*7 + py)*7 + px

    const int px = p % 7;  p /= 7;
    const int py = p % 7;  p /= 7;
    const int r  = p & 15; const int b = p >> 4;

    const int x0 = (r & 3) << 4;          // ROI origin
    const int y0 = (r >> 2) << 4;

    // jax.image.resize bilinear (antialias=False): src = (dst + 0.5) * 16/7 - 0.5
    const float sc = 16.0f / 7.0f;
    const float fy = (py + 0.5f) * sc - 0.5f;
    const float fx = (px + 0.5f) * sc - 0.5f;
    const int   iy = (int)fy;             // floors in [0,14] -> iy+1 <= 15, no clamp needed
    const int   ix = (int)fx;
    const float wy = fy - (float)iy;
    const float wx = fx - (float)ix;

    // float4-granular addressing: 128 float4 per pixel, x stride 128, y stride 64*128
    const float4* __restrict__ in4 = (const float4*)img;
    float4* __restrict__ out4 = (float4*)out;

    const long base = (((long)b * 64 + (y0 + iy)) * 64 + (x0 + ix)) * 128 + tid;

    // 4 independent loads issued up front (MLP=4)
    const float4 v00 = in4[base];
    const float4 v01 = in4[base + 128];
    const float4 v10 = in4[base + 64 * 128];
    const float4 v11 = in4[base + 64 * 128 + 128];

    const float w00 = (1.0f - wy) * (1.0f - wx);
    const float w01 = (1.0f - wy) * wx;
    const float w10 = wy * (1.0f - wx);
    const float w11 = wy * wx;

    float4 o;
    o.x = v00.x * w00 + v01.x * w01 + v10.x * w10 + v11.x * w11;
    o.y = v00.y * w00 + v01.y * w01 + v10.y * w10 + v11.y * w11;
    o.z = v00.z * w00 + v01.z * w01 + v10.z * w10 + v11.z * w11;
    o.w = v00.w * w00 + v01.w * w01 + v10.w * w10 + v11.w * w11;

    out4[(long)blockIdx.x * 128 + tid] = o;
}

extern "C" void kernel_launch(void* const* d_in, const int* in_sizes, int n_in,
                              void* d_out, int out_size) {
    const float* img = (const float*)d_in[0];
    float* out = (float*)d_out;
    // 16 batch * 16 rois * 7 * 7 = 12544 output pixels
    roi_resize_kernel<<<12544, 128>>>(img, out);
}